// round 10
// baseline (speedup 1.0000x reference)
#include <cuda_runtime.h>
#include <cuda_bf16.h>
#include <mma.h>
#include <math.h>
#include <stdint.h>

#define NN   50000
#define EE   100000
#define GG   2048
#define TILE 128
#define NBLK ((NN + TILE - 1) / TILE)     // 391

using namespace nvcuda;
typedef unsigned long long ull;
typedef __nv_bfloat16 bf16;

// ---------------- device scratch ----------------
__device__ float g_h[NN * 32];
__device__ float g_aggr[NN * 32];
__device__ float g_Y[(size_t)NN * 160];   // [node][j*32+o]
__device__ float g_pool[GG * 32];
__device__ float g_cnt[GG];

// fp32 msg-weight table for scalar k_init: [k][j*32+o]
__device__ float W_MS[32 * 160];

// packed bf16 hi/lo B table, row-major [k=0..31][n=0..383]
//   cols 0..127  : [root_w | wh(r,z,n)]   (GEMM1)
//   cols 128..223: wi(r,z,n)              (GEMM2)
//   cols 224..383: msg mats j0..3 + bias  (GEMM3)
__device__ __align__(16) bf16 WBH[32 * 384];
__device__ __align__(16) bf16 WBL[32 * 384];

// ---------------- smem layout (bytes) ----------------
#define S_A_HI 0                 // 128x32 bf16 = 8192
#define S_A_LO 8192
#define S_BH   16384             // 32x384 bf16 = 24576
#define S_BL   40960
#define S_D1   65536             // 128x128 f32 = 65536
#define S_D2   131072            // 128x96  f32 = 49152
#define S_D3   65536             // 128x160 f32 = 81920 (reuses D1+part of D2)
#define SMEM_TC 180224

// ---------------- f32x2 helpers (scalar kernels) ----------------
__device__ __forceinline__ ull ffma2(ull a, ull b, ull c) {
    ull d;
    asm("fma.rn.f32x2 %0, %1, %2, %3;" : "=l"(d) : "l"(a), "l"(b), "l"(c));
    return d;
}
__device__ __forceinline__ ull dup2(float w) {
    ull r;
    asm("mov.b64 %0, {%1, %1};" : "=l"(r) : "f"(w));
    return r;
}
__device__ __forceinline__ float flo(ull v) { return __uint_as_float((unsigned)v); }
__device__ __forceinline__ float fhi(ull v) { return __uint_as_float((unsigned)(v >> 32)); }

// ---------------- K_pack ----------------
__global__ void k_pack(const float* __restrict__ root_w,  // [32,32]
                       const float* __restrict__ wi,      // [96,32]
                       const float* __restrict__ wh,      // [96,32]
                       const float* __restrict__ nn_w,    // [1024,4]
                       const float* __restrict__ nn_b) {  // [1024]
    int gid = blockIdx.x * blockDim.x + threadIdx.x;
    if (gid < GG * 32) g_pool[gid] = 0.0f;
    if (gid < GG) g_cnt[gid] = 0.0f;

    if (gid < 32 * 160) {                // W_MS fp32 for k_init
        int k = gid / 160, jo = gid % 160;
        int j = jo >> 5, o = jo & 31;
        W_MS[gid] = (j < 4) ? nn_w[(k * 32 + o) * 4 + j] : nn_b[k * 32 + o];
    }

    if (gid < 32 * 384) {
        int k = gid / 384, n = gid % 384;
        float w;
        if (n < 32)        w = root_w[k * 32 + n];
        else if (n < 128)  w = wh[(n - 32) * 32 + k];
        else if (n < 224)  w = wi[(n - 128) * 32 + k];
        else {
            int jo = n - 224, j = jo >> 5, o = jo & 31;
            w = (j < 4) ? nn_w[(k * 32 + o) * 4 + j] : nn_b[k * 32 + o];
        }
        bf16 hi = __float2bfloat16(w);
        bf16 lo = __float2bfloat16(w - __bfloat162float(hi));
        WBH[gid] = hi;
        WBL[gid] = lo;
    }
}

// ---------------- K_init: h0 = relu(lin0); Y0 scalar; zero aggr ----------------
__global__ __launch_bounds__(256, 2) void k_init(const float* __restrict__ x,
                                                 const float* __restrict__ w,   // [32,11]
                                                 const float* __restrict__ b) { // [32]
    __shared__ __align__(16) float sh[32][68];
    int t = threadIdx.x, wrp = t >> 5, lane = t & 31;
    int n0 = blockIdx.x * 64 + wrp * 8;
    int colbase = wrp * 8;

    float bias = __ldg(&b[lane]);
    float wv[11];
#pragma unroll
    for (int f = 0; f < 11; f++) wv[f] = __ldg(&w[lane * 11 + f]);

#pragma unroll
    for (int n = 0; n < 8; n++) {
        int node = n0 + n;
        float s = bias;
        if (node < NN) {
#pragma unroll
            for (int f = 0; f < 11; f++) s += __ldg(&x[node * 11 + f]) * wv[f];
        }
        float h = fmaxf(s, 0.0f);
        sh[lane][colbase + n] = h;
        if (node < NN) {
            g_h[node * 32 + lane] = h;
            g_aggr[node * 32 + lane] = 0.0f;
        }
    }
    __syncwarp();

    ull Yk[4][5];
#pragma unroll
    for (int q = 0; q < 4; q++)
#pragma unroll
        for (int j = 0; j < 5; j++) Yk[q][j] = 0ull;
#pragma unroll 8
    for (int k = 0; k < 32; k++) {
        ulonglong2 o01 = *(const ulonglong2*)&sh[k][colbase];
        ulonglong2 o23 = *(const ulonglong2*)&sh[k][colbase + 4];
#pragma unroll
        for (int j = 0; j < 5; j++) {
            ull w2 = dup2(__ldg(&W_MS[k * 160 + j * 32 + lane]));
            Yk[0][j] = ffma2(o01.x, w2, Yk[0][j]);
            Yk[1][j] = ffma2(o01.y, w2, Yk[1][j]);
            Yk[2][j] = ffma2(o23.x, w2, Yk[2][j]);
            Yk[3][j] = ffma2(o23.y, w2, Yk[3][j]);
        }
    }
#pragma unroll
    for (int n = 0; n < 8; n++) {
        int node = n0 + n;
        if (node < NN) {
#pragma unroll
            for (int j = 0; j < 5; j++) {
                float v = (n & 1) ? fhi(Yk[n >> 1][j]) : flo(Yk[n >> 1][j]);
                g_Y[(size_t)node * 160 + j * 32 + lane] = v;
            }
        }
    }
}

// ---------------- K_edge: 2 edges per warp ----------------
__global__ void k_edge(const int* __restrict__ ei,        // [2,E]
                       const float* __restrict__ ea) {    // [E,4]
    int gt   = blockIdx.x * blockDim.x + threadIdx.x;
    int wrp  = gt >> 5;
    int lane = gt & 31;
    int e0   = wrp * 2;
    if (e0 >= EE) return;

    int s0 = __ldg(&ei[e0]);
    int d0 = __ldg(&ei[EE + e0]);
    float4 a0 = __ldg(&reinterpret_cast<const float4*>(ea)[e0]);
    const float* yb0 = &g_Y[(size_t)s0 * 160];

    bool has1 = (e0 + 1) < EE;
    int s1 = has1 ? __ldg(&ei[e0 + 1]) : s0;
    int d1 = has1 ? __ldg(&ei[EE + e0 + 1]) : d0;
    float4 a1 = has1 ? __ldg(&reinterpret_cast<const float4*>(ea)[e0 + 1]) : a0;
    const float* yb1 = &g_Y[(size_t)s1 * 160];

    float v0b = __ldg(&yb0[128 + lane]);
    float v00 = __ldg(&yb0[0   + lane]);
    float v01 = __ldg(&yb0[32  + lane]);
    float v02 = __ldg(&yb0[64  + lane]);
    float v03 = __ldg(&yb0[96  + lane]);
    float v1b = __ldg(&yb1[128 + lane]);
    float v10 = __ldg(&yb1[0   + lane]);
    float v11 = __ldg(&yb1[32  + lane]);
    float v12 = __ldg(&yb1[64  + lane]);
    float v13 = __ldg(&yb1[96  + lane]);

    float m0 = v0b + a0.x * v00 + a0.y * v01 + a0.z * v02 + a0.w * v03;
    atomicAdd(&g_aggr[d0 * 32 + lane], m0);
    if (has1) {
        float m1 = v1b + a1.x * v10 + a1.y * v11 + a1.z * v12 + a1.w * v13;
        atomicAdd(&g_aggr[d1 * 32 + lane], m1);
    }
}

// ---------------- WMMA GEMM: D[m][n] += split3(A) @ split3(B) ----------------
// A: 128x32 bf16 hi/lo (ld 32). B: smem table ld 384 at col bcol0, width ntiles*16.
__device__ __forceinline__ void wmma_gemm(const bf16* AH, const bf16* AL,
                                          const bf16* BH, const bf16* BL,
                                          float* D, int ldD,
                                          int bcol0, int ntiles, int mtile) {
    wmma::fragment<wmma::matrix_a, 16, 16, 16, bf16, wmma::row_major> aH0, aH1, aL0, aL1;
    wmma::load_matrix_sync(aH0, AH + mtile * 16 * 32,      32);
    wmma::load_matrix_sync(aH1, AH + mtile * 16 * 32 + 16, 32);
    wmma::load_matrix_sync(aL0, AL + mtile * 16 * 32,      32);
    wmma::load_matrix_sync(aL1, AL + mtile * 16 * 32 + 16, 32);
    for (int nt = 0; nt < ntiles; nt++) {
        wmma::fragment<wmma::matrix_b, 16, 16, 16, bf16, wmma::row_major> bH0, bH1, bL0, bL1;
        int bc = bcol0 + nt * 16;
        wmma::load_matrix_sync(bH0, BH + bc,            384);
        wmma::load_matrix_sync(bH1, BH + 16 * 384 + bc, 384);
        wmma::load_matrix_sync(bL0, BL + bc,            384);
        wmma::load_matrix_sync(bL1, BL + 16 * 384 + bc, 384);
        wmma::fragment<wmma::accumulator, 16, 16, 16, float> c;
        wmma::fill_fragment(c, 0.0f);
        wmma::mma_sync(c, aH0, bH0, c);
        wmma::mma_sync(c, aH1, bH1, c);
        wmma::mma_sync(c, aH0, bL0, c);
        wmma::mma_sync(c, aH1, bL1, c);
        wmma::mma_sync(c, aL0, bH0, c);
        wmma::mma_sync(c, aL1, bH1, c);
        wmma::store_matrix_sync(D + mtile * 16 * ldD + nt * 16, c, ldD, wmma::mem_row_major);
    }
}

__device__ __forceinline__ void split_store(bf16* AH, bf16* AL, int idx, float v) {
    bf16 hi = __float2bfloat16(v);
    bf16 lo = __float2bfloat16(v - __bfloat162float(hi));
    AH[idx] = hi;
    AL[idx] = lo;
}

// ---------------- K_node_tc: 3 chained WMMA GEMMs + GRU ----------------
__global__ void k_node_tc(const float* __restrict__ conv_b, // [32]
                          const float* __restrict__ bi,     // [96]
                          const float* __restrict__ bh,     // [96]
                          const int* __restrict__ batch,
                          int last) {
    extern __shared__ __align__(32) char smem[];
    bf16*  AH = (bf16*)(smem + S_A_HI);
    bf16*  AL = (bf16*)(smem + S_A_LO);
    bf16*  BH = (bf16*)(smem + S_BH);
    bf16*  BL = (bf16*)(smem + S_BL);
    float* D1 = (float*)(smem + S_D1);    // ld 128
    float* D2 = (float*)(smem + S_D2);    // ld 96
    float* D3 = (float*)(smem + S_D3);    // ld 160

    int t = threadIdx.x, warp = t >> 5;
    int nd = t >> 1, part = t & 1;        // 2 threads per node, 16 dims each
    int node = blockIdx.x * TILE + nd;
    bool valid = node < NN;
    int dbase = part * 16;

    // copy packed B tables (48 KB) as float4
    {
        const float4* sh4 = (const float4*)WBH;
        const float4* sl4 = (const float4*)WBL;
        float4* dh4 = (float4*)BH;
        float4* dl4 = (float4*)BL;
#pragma unroll
        for (int i = 0; i < 6; i++) {
            dh4[t + i * 256] = sh4[t + i * 256];
            dl4[t + i * 256] = sl4[t + i * 256];
        }
    }

    // load h, split into A tiles
    float hv[16];
#pragma unroll
    for (int c = 0; c < 16; c++) {
        hv[c] = valid ? g_h[(size_t)node * 32 + dbase + c] : 0.0f;
        split_store(AH, AL, nd * 32 + dbase + c, hv[c]);
    }
    __syncthreads();

    // GEMM1: D1[128][128] = h @ [root | wh]
    wmma_gemm(AH, AL, BH, BL, D1, 128, 0, 8, warp);
    __syncthreads();

    // epilogue 1: m = relu(aggr + D1[:,0:32] + conv_b); stage into A tiles
#pragma unroll
    for (int c = 0; c < 16; c++) {
        int idx = dbase + c;
        float m = 0.0f;
        if (valid) {
            float a = g_aggr[(size_t)node * 32 + idx];
            g_aggr[(size_t)node * 32 + idx] = 0.0f;   // pre-zero for next round
            m = fmaxf(a + D1[nd * 128 + idx] + __ldg(&conv_b[idx]), 0.0f);
        }
        split_store(AH, AL, nd * 32 + idx, m);
    }
    __syncthreads();

    // GEMM2: D2[128][96] = m @ wi
    wmma_gemm(AH, AL, BH, BL, D2, 96, 128, 6, warp);
    __syncthreads();

    // GRU epilogue
    float hn[16];
#pragma unroll
    for (int c = 0; c < 16; c++) {
        int idx = dbase + c;
        float gir = D2[nd * 96 + idx];
        float giz = D2[nd * 96 + 32 + idx];
        float gin = D2[nd * 96 + 64 + idx];
        float ghr = D1[nd * 128 + 32 + idx];
        float ghz = D1[nd * 128 + 64 + idx];
        float ghn = D1[nd * 128 + 96 + idx];
        float r = 1.0f / (1.0f + __expf(-(gir + __ldg(&bi[idx]) + ghr + __ldg(&bh[idx]))));
        float z = 1.0f / (1.0f + __expf(-(giz + __ldg(&bi[32 + idx]) + ghz + __ldg(&bh[32 + idx]))));
        float nv = tanhf(gin + __ldg(&bi[64 + idx]) + r * (ghn + __ldg(&bh[64 + idx])));
        hn[c] = (1.0f - z) * nv + z * hv[c];
        if (valid) g_h[(size_t)node * 32 + idx] = hn[c];
    }

    if (!last) {
        __syncthreads();   // D1/D2 reads done before D3 overwrites
#pragma unroll
        for (int c = 0; c < 16; c++)
            split_store(AH, AL, nd * 32 + dbase + c, hn[c]);
        __syncthreads();

        // GEMM3: D3[128][160] = hn @ [msg0..3 | bias]
        wmma_gemm(AH, AL, BH, BL, D3, 160, 224, 10, warp);
        __syncthreads();

        // write g_Y coalesced (40 float4 per node, 20 per thread)
        if (valid) {
            float4* yp = (float4*)(g_Y + (size_t)node * 160);
            const float4* dp = (const float4*)(D3 + nd * 160);
#pragma unroll
            for (int q = 0; q < 20; q++) {
                int i4 = part * 20 + q;
                yp[i4] = dp[i4];
            }
        }
    } else {
        if (valid) {
            int bg = __ldg(&batch[node]);
#pragma unroll
            for (int c = 0; c < 16; c++)
                atomicAdd(&g_pool[bg * 32 + dbase + c], hn[c]);
            if (part == 0) atomicAdd(&g_cnt[bg], 1.0f);
        }
    }
}

// ---------------- K_final ----------------
__global__ void k_final(const float* __restrict__ w,   // [2,32]
                        const float* __restrict__ b,   // [2]
                        float* __restrict__ out) {     // [G,2]
    int g = blockIdx.x * blockDim.x + threadIdx.x;
    if (g >= GG) return;
    float inv = 1.0f / fmaxf(g_cnt[g], 1.0f);
    float l0 = b[0], l1 = b[1];
#pragma unroll
    for (int d = 0; d < 32; d++) {
        float p = g_pool[g * 32 + d] * inv;
        l0 += p * w[d];
        l1 += p * w[32 + d];
    }
    float mx  = fmaxf(l0, l1);
    float lse = mx + logf(__expf(l0 - mx) + __expf(l1 - mx));
    out[g * 2 + 0] = l0 - lse;
    out[g * 2 + 1] = l1 - lse;
}

// ---------------- launch ----------------
extern "C" void kernel_launch(void* const* d_in, const int* in_sizes, int n_in,
                              void* d_out, int out_size) {
    const float* x        = (const float*)d_in[0];
    const float* edge_attr= (const float*)d_in[1];
    const float* lin0_w   = (const float*)d_in[2];
    const float* lin0_b   = (const float*)d_in[3];
    const float* nn_w     = (const float*)d_in[4];
    const float* nn_b     = (const float*)d_in[5];
    const float* root_w   = (const float*)d_in[6];
    const float* conv_b   = (const float*)d_in[7];
    const float* gru_wi   = (const float*)d_in[8];
    const float* gru_wh   = (const float*)d_in[9];
    const float* gru_bi   = (const float*)d_in[10];
    const float* gru_bh   = (const float*)d_in[11];
    const float* lin1_w   = (const float*)d_in[12];
    const float* lin1_b   = (const float*)d_in[13];
    const int*   edge_idx = (const int*)d_in[14];
    const int*   batch    = (const int*)d_in[15];
    float* out = (float*)d_out;

    cudaFuncSetAttribute(k_node_tc, cudaFuncAttributeMaxDynamicSharedMemorySize, SMEM_TC);

    const int TPB = 256;
    const int initBlocks = (NN + 63) / 64;                           // 782
    const int edgeWarpBlocks = ((EE + 1) / 2 * 32 + TPB - 1) / TPB;  // 6250
    const int packBlocks = (GG * 32 + TPB - 1) / TPB;                // 256

    k_pack<<<packBlocks, TPB>>>(root_w, gru_wi, gru_wh, nn_w, nn_b);
    k_init<<<initBlocks, TPB>>>(x, lin0_w, lin0_b);

    for (int round = 0; round < 3; round++) {
        k_edge<<<edgeWarpBlocks, TPB>>>(edge_idx, edge_attr);
        k_node_tc<<<NBLK, TPB, SMEM_TC>>>(conv_b, gru_bi, gru_bh, batch, round == 2);
    }

    k_final<<<(GG + TPB - 1) / TPB, TPB>>>(lin1_w, lin1_b, out);
}

// round 11
// speedup vs baseline: 2.5510x; 2.5510x over previous
#include <cuda_runtime.h>
#include <math.h>

#define NN   50000
#define EE   100000
#define GG   2048

typedef unsigned long long ull;

// ---------------- device scratch ----------------
__device__ float g_h[NN * 32];
__device__ float g_aggr[NN * 32];
__device__ float g_Y[(size_t)NN * 160];   // [node][j*32+o]
__device__ float g_pool[GG * 32];
__device__ float g_cnt[GG];

// weight tables
__device__ __align__(16) float P_MS[5120];   // pair-packed for k_init: [((i4*5+j)*32+lane)*4 + (i&3)]
__device__ float W_G[64 * 96];               // k-major GRU: [k][g] k<32->wi, k>=32->wh
__device__ float W_MS[32 * 160];             // k-major msg: [k][j*32+o]

// ---------------- f32x2 helpers ----------------
__device__ __forceinline__ ull ffma2(ull a, ull b, ull c) {
    ull d;
    asm("fma.rn.f32x2 %0, %1, %2, %3;" : "=l"(d) : "l"(a), "l"(b), "l"(c));
    return d;
}
__device__ __forceinline__ ull dup2(float w) {
    ull r;
    asm("mov.b64 %0, {%1, %1};" : "=l"(r) : "f"(w));
    return r;
}
__device__ __forceinline__ float flo(ull v) { return __uint_as_float((unsigned)v); }
__device__ __forceinline__ float fhi(ull v) { return __uint_as_float((unsigned)(v >> 32)); }

// ---------------- K_pack: zero pool + build all weight tables ----------------
__global__ void k_pack(const float* __restrict__ wi,     // [96,32]
                       const float* __restrict__ wh,     // [96,32]
                       const float* __restrict__ nn_w,   // [1024,4]
                       const float* __restrict__ nn_b) { // [1024]
    int gid = blockIdx.x * blockDim.x + threadIdx.x;
    if (gid < GG * 32) g_pool[gid] = 0.0f;
    if (gid < GG) g_cnt[gid] = 0.0f;

    if (gid < 6144) {                        // W_G
        int k = gid / 96, g = gid % 96;
        W_G[gid] = (k < 32) ? wi[g * 32 + k] : wh[g * 32 + (k - 32)];
    } else if (gid < 6144 + 5120) {          // W_MS
        int t2 = gid - 6144;
        int k = t2 / 160, jo = t2 % 160;
        int j = jo >> 5, o = jo & 31;
        W_MS[t2] = (j < 4) ? nn_w[(k * 32 + o) * 4 + j] : nn_b[k * 32 + o];
    } else if (gid < 11264 + 5120) {         // P_MS (pair-packed for k_init)
        int t2 = gid - 11264;
        int pos = t2 & 3;
        int tmp = t2 >> 2;
        int lane = tmp & 31;
        int j = (tmp >> 5) % 5;
        int i4 = (tmp >> 5) / 5;
        int i = i4 * 4 + pos;
        P_MS[t2] = (j < 4) ? nn_w[(i * 32 + lane) * 4 + j] : nn_b[i * 32 + lane];
    }
}

// ---------------- K_init (R5 version): h0 = relu(lin0); Y0; zero aggr ----------------
// 8 warps, 8 nodes/warp -> 64 nodes/block
__global__ __launch_bounds__(256, 2) void k_init(const float* __restrict__ x,
                                                 const float* __restrict__ w,   // [32,11]
                                                 const float* __restrict__ b) { // [32]
    __shared__ __align__(16) float hsm[8][8][32];
    int t = threadIdx.x, wrp = t >> 5, lane = t & 31;
    int n0 = blockIdx.x * 64 + wrp * 8;
    float (*row)[32] = hsm[wrp];

    float bias = __ldg(&b[lane]);
    float wv[11];
#pragma unroll
    for (int f = 0; f < 11; f++) wv[f] = __ldg(&w[lane * 11 + f]);

    float hn[8];
#pragma unroll
    for (int n = 0; n < 8; n++) {
        int node = n0 + n;
        float s = bias;
        if (node < NN) {
#pragma unroll
            for (int f = 0; f < 11; f++) s += __ldg(&x[node * 11 + f]) * wv[f];
        }
        hn[n] = fmaxf(s, 0.0f);
        row[n][lane] = hn[n];
    }
    __syncwarp();

    ull y[8][5];
#pragma unroll
    for (int n = 0; n < 8; n++)
#pragma unroll
        for (int j = 0; j < 5; j++) y[n][j] = 0ull;

#pragma unroll
    for (int i4 = 0; i4 < 8; i4++) {
        ulonglong2 mw[5];
#pragma unroll
        for (int j = 0; j < 5; j++)
            mw[j] = *(const ulonglong2*)&P_MS[((i4 * 5 + j) * 32 + lane) * 4];
#pragma unroll
        for (int n = 0; n < 8; n++) {
            ulonglong2 h2 = *(const ulonglong2*)&row[n][i4 * 4];
#pragma unroll
            for (int j = 0; j < 5; j++) {
                y[n][j] = ffma2(h2.x, mw[j].x, y[n][j]);
                y[n][j] = ffma2(h2.y, mw[j].y, y[n][j]);
            }
        }
    }
#pragma unroll
    for (int n = 0; n < 8; n++) {
        int node = n0 + n;
        if (node >= NN) break;
        g_h[node * 32 + lane] = hn[n];
        g_aggr[node * 32 + lane] = 0.0f;
        float* yb = &g_Y[(size_t)node * 160];
#pragma unroll
        for (int j = 0; j < 5; j++) yb[j * 32 + lane] = flo(y[n][j]) + fhi(y[n][j]);
    }
}

// ---------------- K_edge: 4 edges per warp, all gathers up front ----------------
__global__ void k_edge(const int* __restrict__ ei,        // [2,E]
                       const float* __restrict__ ea) {    // [E,4]
    int gt   = blockIdx.x * blockDim.x + threadIdx.x;
    int wrp  = gt >> 5;
    int lane = gt & 31;
    int e0   = wrp * 4;
    if (e0 >= EE) return;     // EE % 4 == 0 -> no partial group

    int s[4], d[4];
    float4 a[4];
#pragma unroll
    for (int i = 0; i < 4; i++) {
        s[i] = __ldg(&ei[e0 + i]);
        d[i] = __ldg(&ei[EE + e0 + i]);
        a[i] = __ldg(&reinterpret_cast<const float4*>(ea)[e0 + i]);
    }
    float v[4][5];
#pragma unroll
    for (int i = 0; i < 4; i++) {
        const float* yb = &g_Y[(size_t)s[i] * 160];
#pragma unroll
        for (int j = 0; j < 5; j++) v[i][j] = __ldg(&yb[j * 32 + lane]);
    }
#pragma unroll
    for (int i = 0; i < 4; i++) {
        float m = v[i][4] + a[i].x * v[i][0] + a[i].y * v[i][1]
                          + a[i].z * v[i][2] + a[i].w * v[i][3];
        atomicAdd(&g_aggr[d[i] * 32 + lane], m);
    }
}

// ---------------- K_node (R7 version): GEMM-tile, 8 warps x 8 nodes ----------------
// lane = output dim. sh rows 0-31 = m (k-major), rows 32-63 = h (k-major).
__global__ __launch_bounds__(256, 2) void k_node(const float* __restrict__ root_w, // [32,32]
                                                 const float* __restrict__ conv_b, // [32]
                                                 const float* __restrict__ bi,     // [96]
                                                 const float* __restrict__ bh,     // [96]
                                                 const int* __restrict__ batch,
                                                 int last) {
    __shared__ __align__(16) float sh[64][68];
    int t = threadIdx.x, wrp = t >> 5, lane = t & 31;
    int n0 = blockIdx.x * 64 + wrp * 8;
    int colbase = wrp * 8;

    // stage h (k-major) + keep in registers; prefetch aggr
    float hreg[8], areg[8];
#pragma unroll
    for (int n = 0; n < 8; n++) {
        int node = n0 + n;
        hreg[n] = (node < NN) ? g_h[node * 32 + lane] : 0.0f;
        sh[32 + lane][colbase + n] = hreg[n];
    }
#pragma unroll
    for (int n = 0; n < 8; n++) {
        int node = n0 + n;
        areg[n] = (node < NN) ? __ldg(&g_aggr[node * 32 + lane]) : 0.0f;
    }
    __syncwarp();

    // --- root matvec: R[o=lane] = sum_k h[k]*root_w[k][o] ---
    ull R[4];
#pragma unroll
    for (int q = 0; q < 4; q++) R[q] = 0ull;
#pragma unroll 8
    for (int k = 0; k < 32; k++) {
        ulonglong2 o01 = *(const ulonglong2*)&sh[32 + k][colbase];
        ulonglong2 o23 = *(const ulonglong2*)&sh[32 + k][colbase + 4];
        ull w2 = dup2(__ldg(&root_w[k * 32 + lane]));
        R[0] = ffma2(o01.x, w2, R[0]);
        R[1] = ffma2(o01.y, w2, R[1]);
        R[2] = ffma2(o23.x, w2, R[2]);
        R[3] = ffma2(o23.y, w2, R[3]);
    }
    float cb = __ldg(&conv_b[lane]);
#pragma unroll
    for (int n = 0; n < 8; n++) {
        float r = (n & 1) ? fhi(R[n >> 1]) : flo(R[n >> 1]);
        float m = fmaxf(r + areg[n] + cb, 0.0f);
        sh[lane][colbase + n] = m;            // m k-major, rows 0-31
        int node = n0 + n;
        if (node < NN) g_aggr[node * 32 + lane] = 0.0f;   // pre-zero for next round
    }
    __syncwarp();

    // --- fused GRU: A=r-gate, B=z-gate, C=inn (m-part), D=hn (h-part) ---
    ull A[4], B[4], C[4], D[4];
#pragma unroll
    for (int q = 0; q < 4; q++) { A[q] = B[q] = C[q] = D[q] = 0ull; }
#pragma unroll 8
    for (int k = 0; k < 32; k++) {            // m rows
        ulonglong2 o01 = *(const ulonglong2*)&sh[k][colbase];
        ulonglong2 o23 = *(const ulonglong2*)&sh[k][colbase + 4];
        ull wr = dup2(__ldg(&W_G[k * 96 + lane]));
        ull wz = dup2(__ldg(&W_G[k * 96 + 32 + lane]));
        ull wn = dup2(__ldg(&W_G[k * 96 + 64 + lane]));
        A[0] = ffma2(o01.x, wr, A[0]); A[1] = ffma2(o01.y, wr, A[1]);
        A[2] = ffma2(o23.x, wr, A[2]); A[3] = ffma2(o23.y, wr, A[3]);
        B[0] = ffma2(o01.x, wz, B[0]); B[1] = ffma2(o01.y, wz, B[1]);
        B[2] = ffma2(o23.x, wz, B[2]); B[3] = ffma2(o23.y, wz, B[3]);
        C[0] = ffma2(o01.x, wn, C[0]); C[1] = ffma2(o01.y, wn, C[1]);
        C[2] = ffma2(o23.x, wn, C[2]); C[3] = ffma2(o23.y, wn, C[3]);
    }
#pragma unroll 8
    for (int k = 32; k < 64; k++) {           // h rows
        ulonglong2 o01 = *(const ulonglong2*)&sh[k][colbase];
        ulonglong2 o23 = *(const ulonglong2*)&sh[k][colbase + 4];
        ull wr = dup2(__ldg(&W_G[k * 96 + lane]));
        ull wz = dup2(__ldg(&W_G[k * 96 + 32 + lane]));
        ull wn = dup2(__ldg(&W_G[k * 96 + 64 + lane]));
        A[0] = ffma2(o01.x, wr, A[0]); A[1] = ffma2(o01.y, wr, A[1]);
        A[2] = ffma2(o23.x, wr, A[2]); A[3] = ffma2(o23.y, wr, A[3]);
        B[0] = ffma2(o01.x, wz, B[0]); B[1] = ffma2(o01.y, wz, B[1]);
        B[2] = ffma2(o23.x, wz, B[2]); B[3] = ffma2(o23.y, wz, B[3]);
        D[0] = ffma2(o01.x, wn, D[0]); D[1] = ffma2(o01.y, wn, D[1]);
        D[2] = ffma2(o23.x, wn, D[2]); D[3] = ffma2(o23.y, wn, D[3]);
    }

    float bir = __ldg(&bi[lane]), biz = __ldg(&bi[lane + 32]), bin = __ldg(&bi[lane + 64]);
    float bhr = __ldg(&bh[lane]), bhz = __ldg(&bh[lane + 32]), bhn = __ldg(&bh[lane + 64]);

    float hn[8];
#pragma unroll
    for (int n = 0; n < 8; n++) {
        int q = n >> 1;
        float ga = (n & 1) ? fhi(A[q]) : flo(A[q]);
        float gb = (n & 1) ? fhi(B[q]) : flo(B[q]);
        float gc = (n & 1) ? fhi(C[q]) : flo(C[q]);
        float gd = (n & 1) ? fhi(D[q]) : flo(D[q]);
        float r  = 1.0f / (1.0f + __expf(-(ga + bir + bhr)));
        float z  = 1.0f / (1.0f + __expf(-(gb + biz + bhz)));
        float nv = tanhf(gc + bin + r * (gd + bhn));
        hn[n] = (1.0f - z) * nv + z * hreg[n];
    }

    if (last) {
#pragma unroll
        for (int n = 0; n < 8; n++) {
            int node = n0 + n;
            if (node < NN) {
                int bg = __ldg(&batch[node]);
                atomicAdd(&g_pool[bg * 32 + lane], hn[n]);
                if (lane == 0) atomicAdd(&g_cnt[bg], 1.0f);
            }
        }
        return;
    }

    // overwrite h rows with hn, store g_h
#pragma unroll
    for (int n = 0; n < 8; n++) {
        sh[32 + lane][colbase + n] = hn[n];
        int node = n0 + n;
        if (node < NN) g_h[node * 32 + lane] = hn[n];
    }
    __syncwarp();

    // Y-GEMM: Y[j][o=lane] = sum_k hn[k] * W_MS[k][j*32+o]
    ull Yk[4][5];
#pragma unroll
    for (int q = 0; q < 4; q++)
#pragma unroll
        for (int j = 0; j < 5; j++) Yk[q][j] = 0ull;
#pragma unroll 8
    for (int k = 0; k < 32; k++) {
        ulonglong2 o01 = *(const ulonglong2*)&sh[32 + k][colbase];
        ulonglong2 o23 = *(const ulonglong2*)&sh[32 + k][colbase + 4];
#pragma unroll
        for (int j = 0; j < 5; j++) {
            ull w2 = dup2(__ldg(&W_MS[k * 160 + j * 32 + lane]));
            Yk[0][j] = ffma2(o01.x, w2, Yk[0][j]);
            Yk[1][j] = ffma2(o01.y, w2, Yk[1][j]);
            Yk[2][j] = ffma2(o23.x, w2, Yk[2][j]);
            Yk[3][j] = ffma2(o23.y, w2, Yk[3][j]);
        }
    }
#pragma unroll
    for (int n = 0; n < 8; n++) {
        int node = n0 + n;
        if (node < NN) {
#pragma unroll
            for (int j = 0; j < 5; j++) {
                float v = (n & 1) ? fhi(Yk[n >> 1][j]) : flo(Yk[n >> 1][j]);
                g_Y[(size_t)node * 160 + j * 32 + lane] = v;
            }
        }
    }
}

// ---------------- K_final: logits + log_softmax ----------------
__global__ void k_final(const float* __restrict__ w,   // [2,32]
                        const float* __restrict__ b,   // [2]
                        float* __restrict__ out) {     // [G,2]
    int g = blockIdx.x * blockDim.x + threadIdx.x;
    if (g >= GG) return;
    float inv = 1.0f / fmaxf(g_cnt[g], 1.0f);
    float l0 = b[0], l1 = b[1];
#pragma unroll
    for (int d = 0; d < 32; d++) {
        float p = g_pool[g * 32 + d] * inv;
        l0 += p * w[d];
        l1 += p * w[32 + d];
    }
    float mx  = fmaxf(l0, l1);
    float lse = mx + logf(__expf(l0 - mx) + __expf(l1 - mx));
    out[g * 2 + 0] = l0 - lse;
    out[g * 2 + 1] = l1 - lse;
}

// ---------------- launch ----------------
extern "C" void kernel_launch(void* const* d_in, const int* in_sizes, int n_in,
                              void* d_out, int out_size) {
    const float* x        = (const float*)d_in[0];
    const float* edge_attr= (const float*)d_in[1];
    const float* lin0_w   = (const float*)d_in[2];
    const float* lin0_b   = (const float*)d_in[3];
    const float* nn_w     = (const float*)d_in[4];
    const float* nn_b     = (const float*)d_in[5];
    const float* root_w   = (const float*)d_in[6];
    const float* conv_b   = (const float*)d_in[7];
    const float* gru_wi   = (const float*)d_in[8];
    const float* gru_wh   = (const float*)d_in[9];
    const float* gru_bi   = (const float*)d_in[10];
    const float* gru_bh   = (const float*)d_in[11];
    const float* lin1_w   = (const float*)d_in[12];
    const float* lin1_b   = (const float*)d_in[13];
    const int*   edge_idx = (const int*)d_in[14];
    const int*   batch    = (const int*)d_in[15];
    float* out = (float*)d_out;

    const int TPB = 256;
    const int nodeBlocks = (NN + 63) / 64;                           // 782
    const int edgeWarpBlocks = ((EE / 4) * 32 + TPB - 1) / TPB;      // 3125
    const int packBlocks = (GG * 32 + TPB - 1) / TPB;                // 256

    k_pack<<<packBlocks, TPB>>>(gru_wi, gru_wh, nn_w, nn_b);
    k_init<<<nodeBlocks, TPB>>>(x, lin0_w, lin0_b);

    for (int round = 0; round < 3; round++) {
        k_edge<<<edgeWarpBlocks, TPB>>>(edge_idx, edge_attr);
        k_node<<<nodeBlocks, TPB>>>(root_w, conv_b, gru_bi, gru_bh, batch, round == 2);
    }

    k_final<<<(GG + TPB - 1) / TPB, TPB>>>(lin1_w, lin1_b, out);
}